// round 2
// baseline (speedup 1.0000x reference)
#include <cuda_runtime.h>
#include <math.h>

// ---------------------------------------------------------------------------
// LabelSmoothing KL-div loss, reduced to a per-row streaming sum + 2 gathers:
//   contrib(row) = C - eps*(rowsum - pred[row][0]) - (0.9 - eps)*pred[row][tgt]
//   (0 if tgt == PAD_IDX)
// where eps = SMOOTHING/(V-2), C = (V-2)*eps*ln(eps) + (1-S)*ln(1-S).
// Single fused kernel: per-row streaming sum + inline dtype detect +
// last-block final reduction. HBM-bound: 262 MB read.
// ---------------------------------------------------------------------------

#define PAD_IDX 0

__device__ double       g_partials[65536];   // per-row contributions
__device__ unsigned int g_count = 0;         // blocks-done counter (self-resetting)

__global__ __launch_bounds__(512) void ls_kernel(
    const float* __restrict__ pred,
    const void*  __restrict__ tgt_raw,
    float* __restrict__ out,
    int N, int V, double eps, double coefC, double w_tgt)
{
    const int row = blockIdx.x;
    const float* __restrict__ p = pred + (size_t)row * (size_t)V;
    const int tid = threadIdx.x;
    const int wid = tid >> 5;
    const int lid = tid & 31;

    __shared__ float        warpsum[16];
    __shared__ int          sh_is64;
    __shared__ unsigned int sh_islast;

    // ---- inline dtype detection (warp 0 only; words [0,64) are safe to read
    //      under both layouts; odd words all-zero <=> int64 little-endian) ----
    if (wid == 0) {
        int idx = 2 * lid + 1;
        int v = (idx < N) ? ((const int*)tgt_raw)[idx] : 0;
        unsigned int nz = __ballot_sync(0xffffffffu, v != 0);
        if (lid == 0) sh_is64 = (nz == 0u) ? 1 : 0;
    }

    // ---- streaming row sum (vectorized, coalesced) ----
    float local = 0.0f;
    const int nv4 = V >> 2;
    const float4* __restrict__ p4 = (const float4*)p;
    #pragma unroll 8
    for (int i = tid; i < nv4; i += blockDim.x) {
        float4 v = p4[i];
        local += (v.x + v.y) + (v.z + v.w);
    }
    for (int i = (nv4 << 2) + tid; i < V; i += blockDim.x)
        local += p[i];

    #pragma unroll
    for (int o = 16; o > 0; o >>= 1)
        local += __shfl_xor_sync(0xffffffffu, local, o);
    if (lid == 0) warpsum[wid] = local;
    __syncthreads();

    // ---- thread 0: assemble analytic row contribution ----
    if (tid == 0) {
        float s = 0.0f;
        const int nw = (int)(blockDim.x + 31) >> 5;
        for (int i = 0; i < nw; i++) s += warpsum[i];

        long long t;
        if (sh_is64) t = ((const long long*)tgt_raw)[row];
        else         t = (long long)((const int*)tgt_raw)[row];

        double o = 0.0;
        if (t != PAD_IDX && t >= 0 && t < (long long)V) {
            const double rowsum_excl0 = (double)s - (double)p[0];
            o = coefC - eps * rowsum_excl0 - w_tgt * (double)p[t];
        }
        g_partials[row] = o;

        __threadfence();
        unsigned int done = atomicAdd(&g_count, 1u);
        sh_islast = (done == (unsigned int)(gridDim.x - 1)) ? 1u : 0u;
    }
    __syncthreads();

    // ---- last block: deterministic tree reduction of all partials ----
    if (sh_islast) {
        __shared__ double ws[16];
        double dl = 0.0;
        for (int i = tid; i < N; i += blockDim.x)
            dl += g_partials[i];
        #pragma unroll
        for (int o = 16; o > 0; o >>= 1)
            dl += __shfl_xor_sync(0xffffffffu, dl, o);
        if (lid == 0) ws[wid] = dl;
        __syncthreads();
        if (tid == 0) {
            double total = 0.0;
            const int nw = (int)(blockDim.x + 31) >> 5;
            for (int i = 0; i < nw; i++) total += ws[i];
            out[0] = (float)total;
            g_count = 0;   // reset for next graph replay
        }
    }
}

extern "C" void kernel_launch(void* const* d_in, const int* in_sizes, int n_in,
                              void* d_out, int out_size)
{
    const float* pred = (const float*)d_in[0];
    const void*  tgt  = d_in[1];

    const int total = in_sizes[0];   // B*S*V
    const int N     = in_sizes[1];   // B*S rows
    const int V     = total / N;

    const double smoothing = 0.1;
    const double eps   = smoothing / (double)(V - 2);
    const double coefC = (double)(V - 2) * eps * log(eps)
                       + (1.0 - smoothing) * log(1.0 - smoothing);
    const double w_tgt = (1.0 - smoothing) - eps;

    ls_kernel<<<N, 512>>>(pred, tgt, (float*)d_out, N, V, eps, coefC, w_tgt);
}

// round 3
// speedup vs baseline: 1.0749x; 1.0749x over previous
#include <cuda_runtime.h>
#include <math.h>

// ---------------------------------------------------------------------------
// LabelSmoothing KL-div loss:
//   contrib(row) = C - eps*(rowsum - p[0]) - (0.9-eps)*p[tgt]   (0 if pad)
// Single-wave launch: 2048 blocks x 128 threads, 16 CTAs/SM => every
// row-block resident simultaneously (no wave quantization).
// HBM-bound: 262 MB streaming read.
// ---------------------------------------------------------------------------

#define PAD_IDX 0

__device__ double       g_partials[65536];
__device__ unsigned int g_count = 0;

__global__ __launch_bounds__(128, 16) void ls_kernel(
    const float* __restrict__ pred,
    const void*  __restrict__ tgt_raw,
    float* __restrict__ out,
    int N, int V, double eps, double coefC, double w_tgt)
{
    const int row = blockIdx.x;
    const float* __restrict__ p = pred + (size_t)row * (size_t)V;
    const int tid = threadIdx.x;
    const int wid = tid >> 5;
    const int lid = tid & 31;

    __shared__ float        warpsum[4];
    __shared__ int          sh_is64;
    __shared__ unsigned int sh_islast;

    // ---- inline dtype detection (warp 0; words [0,64) safe under both
    //      layouts; odd int32 words all-zero <=> int64 little-endian) ----
    if (wid == 0) {
        int idx = 2 * lid + 1;
        int v = (idx < N) ? ((const int*)tgt_raw)[idx] : 0;
        unsigned int nz = __ballot_sync(0xffffffffu, v != 0);
        if (lid == 0) sh_is64 = (nz == 0u) ? 1 : 0;
    }

    // ---- streaming row sum: 4 independent accumulators ----
    const int nv4 = V >> 2;
    const float4* __restrict__ p4 = (const float4*)p;
    float a0 = 0.0f, a1 = 0.0f, a2 = 0.0f, a3 = 0.0f;
    int i = tid;
    const int bd = blockDim.x;
    for (; i + 3 * bd < nv4; i += 4 * bd) {
        float4 v0 = p4[i];
        float4 v1 = p4[i + bd];
        float4 v2 = p4[i + 2 * bd];
        float4 v3 = p4[i + 3 * bd];
        a0 += (v0.x + v0.y) + (v0.z + v0.w);
        a1 += (v1.x + v1.y) + (v1.z + v1.w);
        a2 += (v2.x + v2.y) + (v2.z + v2.w);
        a3 += (v3.x + v3.y) + (v3.z + v3.w);
    }
    for (; i < nv4; i += bd) {
        float4 v = p4[i];
        a0 += (v.x + v.y) + (v.z + v.w);
    }
    for (int j = (nv4 << 2) + tid; j < V; j += bd)
        a0 += p[j];

    float local = (a0 + a1) + (a2 + a3);
    #pragma unroll
    for (int o = 16; o > 0; o >>= 1)
        local += __shfl_xor_sync(0xffffffffu, local, o);
    if (lid == 0) warpsum[wid] = local;
    __syncthreads();

    // ---- thread 0: assemble analytic row contribution ----
    if (tid == 0) {
        float s = (warpsum[0] + warpsum[1]) + (warpsum[2] + warpsum[3]);

        long long t;
        if (sh_is64) t = ((const long long*)tgt_raw)[row];
        else         t = (long long)((const int*)tgt_raw)[row];

        double o = 0.0;
        if (t != PAD_IDX && t >= 0 && t < (long long)V) {
            const double rowsum_excl0 = (double)s - (double)__ldg(&p[0]);
            o = coefC - eps * rowsum_excl0 - w_tgt * (double)__ldg(&p[t]);
        }
        g_partials[row] = o;

        __threadfence();
        unsigned int done = atomicAdd(&g_count, 1u);
        sh_islast = (done == (unsigned int)(gridDim.x - 1)) ? 1u : 0u;
    }
    __syncthreads();

    // ---- last block: deterministic tree reduction of all partials ----
    if (sh_islast) {
        __shared__ double ws[4];
        double dl = 0.0;
        for (int k = tid; k < N; k += bd)
            dl += g_partials[k];
        #pragma unroll
        for (int o = 16; o > 0; o >>= 1)
            dl += __shfl_xor_sync(0xffffffffu, dl, o);
        if (lid == 0) ws[wid] = dl;
        __syncthreads();
        if (tid == 0) {
            double total = (ws[0] + ws[1]) + (ws[2] + ws[3]);
            out[0] = (float)total;
            g_count = 0;   // reset for next graph replay
        }
    }
}

extern "C" void kernel_launch(void* const* d_in, const int* in_sizes, int n_in,
                              void* d_out, int out_size)
{
    const float* pred = (const float*)d_in[0];
    const void*  tgt  = d_in[1];

    const int total = in_sizes[0];   // B*S*V
    const int N     = in_sizes[1];   // B*S rows
    const int V     = total / N;

    const double smoothing = 0.1;
    const double eps   = smoothing / (double)(V - 2);
    const double coefC = (double)(V - 2) * eps * log(eps)
                       + (1.0 - smoothing) * log(1.0 - smoothing);
    const double w_tgt = (1.0 - smoothing) - eps;

    ls_kernel<<<N, 128>>>(pred, tgt, (float*)d_out, N, V, eps, coefC, w_tgt);
}